// round 17
// baseline (speedup 1.0000x reference)
#include <cuda_runtime.h>
#include <cstdint>

// Fixed shapes
#define B_TOTAL   65536
#define P_DIM     41
#define NROWS     (B_TOTAL * P_DIM)        // 2686976 rows of 4 lanes (L=4)
#define THREADS   256
#define WARPS_PB  8
#define USEFUL    28                        // useful rows per warp-chunk (lanes 2..29)
#define CHUNKS    ((NROWS + USEFUL - 1) / USEFUL)   // 95964
#define GRID      512                       // persistent CTAs (< 592 residency slots)
#define WTOT      (GRID * WARPS_PB)         // 4096 warps, grid-stride over chunks

__device__ float        g_partials[GRID];
__device__ unsigned int g_count = 0;        // ticket; returns to 0 every launch

struct Row {
    float4 v0, v1;
    int4   tg;
    int    rl;
};

__device__ __forceinline__ Row load_row(const float4* __restrict__ gL,
                                        const int4* __restrict__ gT, int rl)
{
    Row x;
    x.rl = rl;
    const int r = min(max(rl, 0), NROWS - 1);
    const int b = (int)((unsigned)r / 41u);
    const int idx0 = r + b * 41;             // = b*82 + p
    x.v0 = __ldcg(gL + idx0);                // class 0
    x.v1 = __ldcg(gL + idx0 + 41);           // class 1
    x.tg = __ldcg(gT + r);
    return x;
}

__global__ __launch_bounds__(THREADS, 4)
void lace_kernel(const float* __restrict__ logits,
                 const int* __restrict__ targets,
                 float* __restrict__ out)
{
    __shared__ float warpsums[WARPS_PB];
    __shared__ float redsums[WARPS_PB];
    __shared__ bool  isLast;

    const int tid   = threadIdx.x;
    const int lane  = tid & 31;
    const int wid   = tid >> 5;
    const int gwarp = blockIdx.x * WARPS_PB + wid;

    const float4* __restrict__ gL = (const float4*)logits;   // 82 float4 per batch
    const int4*   __restrict__ gT = (const int4*)targets;    // 1 int4 per row

    const bool laneOK = (lane >= 2 && lane <= 29);

    float acc     = 0.0f;
    int   connAcc = 0;

    // persistent grid-stride over 28-row chunks; depth-2 register pipeline
    int k = gwarp;
    Row cur = load_row(gL, gT, k * USEFUL + lane - 2);

    while (k < CHUNKS) {
        const int kn = k + WTOT;                       // warp-uniform
        Row nxt = (kn < CHUNKS) ? load_row(gL, gT, kn * USEFUL + lane - 2) : cur;

        // ---- compute on cur ----
        const int rl = cur.rl;
        const int r  = min(max(rl, 0), NROWS - 1);
        const int p  = r - (int)((unsigned)r / 41u) * 41;
        const bool valid = laneOK && (rl < NROWS);

        const float ne0 = cur.v0.x - cur.v1.x, ne1 = cur.v0.y - cur.v1.y;
        const float ne2 = cur.v0.z - cur.v1.z, ne3 = cur.v0.w - cur.v1.w;

        // pk: per-l byte, bit6 = target, bit7 = pred (l1>l0 <=> ne<0)
        unsigned pa = __byte_perm((unsigned)cur.tg.x, (unsigned)cur.tg.y, 0x0040);
        unsigned pb = __byte_perm((unsigned)cur.tg.z, (unsigned)cur.tg.w, 0x0040);
        unsigned sT = __byte_perm(pa, pb, 0x5410);
        unsigned qa = __byte_perm(__float_as_uint(ne0), __float_as_uint(ne1), 0x0073);
        unsigned qb = __byte_perm(__float_as_uint(ne2), __float_as_uint(ne3), 0x0073);
        unsigned sP = __byte_perm(qa, qb, 0x5410);
        unsigned pk = (sT << 6) | (sP & 0x80808080u);

        // batch-boundary-clamped shuffle sources (clamp-to-self zeroes the xor)
        int sm1 = (p == 0)          ? lane : lane - 1;
        int sm2 = (p <= 1)          ? lane : lane - 2;
        int sp1 = (p == P_DIM - 1)  ? lane : lane + 1;
        int sp2 = (p >= P_DIM - 2)  ? lane : lane + 2;

        unsigned pkm1 = __shfl_sync(0xffffffffu, pk, sm1);
        unsigned pkm2 = __shfl_sync(0xffffffffu, pk, sm2);
        unsigned pkp1 = __shfl_sync(0xffffffffu, pk, sp1);
        unsigned pkp2 = __shfl_sync(0xffffffffu, pk, sp2);

        unsigned xm1 = pk ^ pkm1;
        unsigned xm2 = pk ^ pkm2;
        unsigned xp1 = pk ^ pkp1;
        unsigned xp2 = pk ^ pkp2;

        // connectivity: pred-xor vs p-1 (bit7/byte), masked, integer accumulate
        unsigned maskC = valid ? 0x80808080u : 0u;
        connAcc += __popc(xm1 & maskC);

        // weight bytes: value = 2w-2 in [0,6] per byte
        unsigned w1 = ((xm1 >> 6) & 0x01010101u) + ((xp1 >> 6) & 0x01010101u);
        unsigned w2 = ((xm2 >> 6) & 0x01010101u) + ((xp2 >> 6) & 0x01010101u);
        unsigned wb = w1 + w1 + w2;

        // mis = t ^ pred at bit7 of each byte
        unsigned misW = (pk << 1) ^ pk;

        const float vf = valid ? 1.0f : 0.0f;
        const float hv = valid ? 0.5f : 0.0f;

        const float nes[4] = {ne0, ne1, ne2, ne3};
        #pragma unroll
        for (int l = 0; l < 4; ++l) {
            float ae = fabsf(nes[l]);
            // softplus(d) = mis*|ne| + log(1 + exp(-|ne|))
            float ex  = __expf(-ae);
            float sp  = __logf(1.0f + ex);
            float z   = ((misW >> (8 * l + 7)) & 1u) ? ae : 0.0f;
            float loss = z + sp;
            float fb  = (float)((wb >> (8 * l)) & 0xFFu);      // 2w-2
            float wf  = fmaf(fb, hv, vf);                      // = valid * w
            acc = fmaf(loss, wf, acc);
        }

        cur = nxt;
        k = kn;
    }

    acc = fmaf(0.001f, (float)connAcc, acc);

    // warp reduce -> block partial
    #pragma unroll
    for (int o = 16; o > 0; o >>= 1)
        acc += __shfl_down_sync(0xffffffffu, acc, o);
    if (lane == 0) warpsums[wid] = acc;
    __syncthreads();

    if (tid == 0) {
        float bs = 0.0f;
        #pragma unroll
        for (int k2 = 0; k2 < WARPS_PB; ++k2) bs += warpsums[k2];
        g_partials[blockIdx.x] = bs;
        __threadfence();
        unsigned int old = atomicAdd(&g_count, 1u);
        isLast = (old == GRID - 1);
    }
    __syncthreads();

    // last block: deterministic fixed-order reduction of 512 partials
    if (isLast) {
        float s = g_partials[tid] + g_partials[tid + THREADS];
        #pragma unroll
        for (int o = 16; o > 0; o >>= 1)
            s += __shfl_down_sync(0xffffffffu, s, o);
        if (lane == 0) redsums[wid] = s;
        __syncthreads();
        if (tid == 0) {
            float t = 0.0f;
            #pragma unroll
            for (int k2 = 0; k2 < WARPS_PB; ++k2) t += redsums[k2];
            out[0] = t * (1.0f / ((float)B_TOTAL * (float)P_DIM * 4.0f));
            g_count = 0;   // reset for next graph replay
        }
    }
}

extern "C" void kernel_launch(void* const* d_in, const int* in_sizes, int n_in,
                              void* d_out, int out_size)
{
    const float* logits  = (const float*)d_in[0];
    const int*   targets = (const int*)d_in[1];
    float*       out     = (float*)d_out;

    lace_kernel<<<GRID, THREADS>>>(logits, targets, out);
}